// round 14
// baseline (speedup 1.0000x reference)
#include <cuda_runtime.h>
#include <cuda_bf16.h>

// Ball query: for each of NQ=32768 query points (p_grid), find first K=10
// points of x (NP=8192) with d2 <= RADIUS^2, ascending index order.
//
// Output (float32): [0..NQ*K) mapping (index as float), [NQ*K..NQ*K*4) coords.
//
// R14: spatial prefilter. 4x4x4 cells of size 0.25. Per cell, an index-sorted
// list of all points within the cell box expanded by 0.25+slop per axis
// (conservative superset of any in-cell query's ball, slop >> d2 rounding).
// Query scans only its cell's list with the EXACT R6 d2 expression and the
// proven ballot/slot logic -> identical decisions, identical order, ~4x fewer
// point tests and a flattened straggler tail. No fallback scan needed.

#define NP 8192
#define NQ 32768
#define KNN 10
#define R2C 0.0625f
#define MAP_ELEMS (NQ * KNN)
#define NCELLS 64
#define MAXN 4224           // expected max list ~3460, +17 sigma headroom
#define SLOPW 0.2501f       // 0.25 + 1e-4 expansion half-width
#define WARPS_PER_CTA 8

__device__ float4 g_nbr[NCELLS][MAXN];
__device__ int    g_lidx[NCELLS][MAXN];
__device__ int    g_cnt[NCELLS];

// cell id = (cx*4 + cy)*4 + cz  -- must match between build and query
__global__ void __launch_bounds__(128)
build_kernel(const float* __restrict__ x)
{
    __shared__ int s_cnt[4];
    const int cell = blockIdx.x;
    const int cz = cell & 3;
    const int cy = (cell >> 2) & 3;
    const int cx = (cell >> 4) & 3;
    const float lox = cx * 0.25f - SLOPW, hix = cx * 0.25f + 0.25f + SLOPW;
    const float loy = cy * 0.25f - SLOPW, hiy = cy * 0.25f + 0.25f + SLOPW;
    const float loz = cz * 0.25f - SLOPW, hiz = cz * 0.25f + 0.25f + SLOPW;

    const int lane = threadIdx.x & 31;
    const int warp = threadIdx.x >> 5;
    const int seg0 = warp * (NP / 4);
    const int seg1 = seg0 + (NP / 4);
    const unsigned lt = (1u << lane) - 1u;

    // pass 1: count this warp's segment
    int c = 0;
    for (int base = seg0; base < seg1; base += 32) {
        const int i = base + lane;
        const float px = x[3 * i + 0];
        const float py = x[3 * i + 1];
        const float pz = x[3 * i + 2];
        const bool in = (px >= lox && px <= hix &&
                         py >= loy && py <= hiy &&
                         pz >= loz && pz <= hiz);
        c += __popc(__ballot_sync(0xffffffffu, in));
    }
    if (lane == 0) s_cnt[warp] = c;
    __syncthreads();

    int off = 0;
    for (int w = 0; w < warp; w++) off += s_cnt[w];

    // pass 2: ordered compact into the cell list (index-sorted overall)
    int cnt = 0;
    for (int base = seg0; base < seg1; base += 32) {
        const int i = base + lane;
        const float px = x[3 * i + 0];
        const float py = x[3 * i + 1];
        const float pz = x[3 * i + 2];
        const bool in = (px >= lox && px <= hix &&
                         py >= loy && py <= hiy &&
                         pz >= loz && pz <= hiz);
        const unsigned m = __ballot_sync(0xffffffffu, in);
        if (in) {
            const int pos = off + cnt + __popc(m & lt);
            if (pos < MAXN) {
                // same ps expression as always
                const float ps = px * px + py * py + pz * pz;
                g_nbr[cell][pos] = make_float4(px, py, pz, ps);
                g_lidx[cell][pos] = i;
            }
        }
        cnt += __popc(m);
    }
    __syncthreads();
    if (threadIdx.x == 0) {
        int tot = s_cnt[0] + s_cnt[1] + s_cnt[2] + s_cnt[3];
        g_cnt[cell] = tot < MAXN ? tot : MAXN;
    }
}

__global__ void __launch_bounds__(256)
bq_kernel(const float* __restrict__ x,
          const float* __restrict__ pg,
          float* __restrict__ out)
{
    __shared__ int scratch[WARPS_PER_CTA][16];

    const int lane   = threadIdx.x & 31;
    const int warp   = threadIdx.x >> 5;
    const int gwarp  = (blockIdx.x * blockDim.x + threadIdx.x) >> 5;
    const int nwarps = (gridDim.x * blockDim.x) >> 5;
    const unsigned lt_mask = (1u << lane) - 1u;

    for (int q = gwarp; q < NQ; q += nwarps) {
        const float qx = pg[3 * q + 0];
        const float qy = pg[3 * q + 1];
        const float qz = pg[3 * q + 2];
        const float q2 = qx * qx + qy * qy + qz * qz;

        int cx = (int)(qx * 4.0f); cx = cx < 0 ? 0 : (cx > 3 ? 3 : cx);
        int cy = (int)(qy * 4.0f); cy = cy < 0 ? 0 : (cy > 3 ? 3 : cy);
        int cz = (int)(qz * 4.0f); cz = cz < 0 ? 0 : (cz > 3 ? 3 : cz);
        const int cell = (cx * 4 + cy) * 4 + cz;
        const int n = g_cnt[cell];
        const float4* __restrict__ lst  = g_nbr[cell];
        const int*    __restrict__ lidx = g_lidx[cell];

        int cnt = 0;

        // scan the cell list, 64 entries / iteration, 2 ILP streams
        for (int base = 0; base < n; base += 64) {
            const int eA = base + lane;
            const int eB = base + 32 + lane;
            // sentinel w=1e30 makes d2 huge -> invalid, no extra predicate
            const float4 A = (eA < n) ? lst[eA] : make_float4(0.f, 0.f, 0.f, 1e30f);
            const float4 B = (eB < n) ? lst[eB] : make_float4(0.f, 0.f, 0.f, 1e30f);

            const float dotA = qx * A.x + qy * A.y + qz * A.z;
            const float d2A  = q2 + A.w - 2.0f * dotA;
            const float dotB = qx * B.x + qy * B.y + qz * B.z;
            const float d2B  = q2 + B.w - 2.0f * dotB;

            const bool vA = (d2A <= R2C);
            const bool vB = (d2B <= R2C);
            const unsigned mA = __ballot_sync(0xffffffffu, vA);
            const unsigned mB = __ballot_sync(0xffffffffu, vB);

            if (mA | mB) {
                if (vA) {
                    const int slot = cnt + __popc(mA & lt_mask);
                    if (slot < KNN) scratch[warp][slot] = eA;   // list position
                }
                const int cA = cnt + __popc(mA);
                if (vB) {
                    const int slot = cA + __popc(mB & lt_mask);
                    if (slot < KNN) scratch[warp][slot] = eB;
                }
                cnt = cA + __popc(mB);
                if (cnt >= KNN) break;   // warp-uniform
            }
        }

        __syncwarp();

        // epilogue: lanes 0..9 emit mapping + coords (reload from list, L1-hot)
        const int c = cnt < KNN ? cnt : KNN;
        if (lane < KNN) {
            const bool found = (lane < c);
            int idx = 0;
            float px = 0.0f, py = 0.0f, pz = 0.0f;
            if (found) {
                const int e = scratch[warp][lane];
                const float4 P = lst[e];
                px = P.x; py = P.y; pz = P.z;
                idx = lidx[e];
            }
            out[(size_t)q * KNN + lane] = found ? (float)idx : 0.0f;
            float* oc = out + MAP_ELEMS + ((size_t)q * KNN + lane) * 3;
            oc[0] = px; oc[1] = py; oc[2] = pz;
        }
        __syncwarp();   // scratch reuse safety
    }
}

extern "C" void kernel_launch(void* const* d_in, const int* in_sizes, int n_in,
                              void* d_out, int out_size)
{
    const float* x  = (const float*)d_in[0];   // (1, 8192, 3)
    const float* pg = (const float*)d_in[1];   // (1, 64, 32, 16, 3)
    if (n_in >= 2 && in_sizes[0] == NQ * 3 && in_sizes[1] == NP * 3) {
        const float* t = x; x = pg; pg = t;
    }
    float* out = (float*)d_out;

    build_kernel<<<NCELLS, 128>>>(x);
    bq_kernel<<<888, 256>>>(x, pg, out);
}

// round 15
// speedup vs baseline: 1.5209x; 1.5209x over previous
#include <cuda_runtime.h>
#include <cuda_bf16.h>

// Ball query: for each of NQ=32768 query points (p_grid), find first K=10
// points of x (NP=8192) with d2 <= RADIUS^2, ascending index order.
//
// Output (float32): [0..NQ*K) mapping (index as float), [NQ*K..NQ*K*4) coords.
//
// R15 = R14 (bq proven at 12.2us) with the build parallelized 8x:
// 512 CTAs = 64 cells x 8 segments of 1024 points. Each CTA derives its
// global write offset by counting the preceding segments (count-only pass),
// then ballot-compacts its own segment in index order. One kernel, no atomics.
// bq additionally caches the 64 cell counts in SMEM.

#define NP 8192
#define NQ 32768
#define KNN 10
#define R2C 0.0625f
#define MAP_ELEMS (NQ * KNN)
#define NCELLS 64
#define MAXN 4224
#define SLOPW 0.2501f       // 0.25 + 1e-4 expansion half-width
#define WARPS_PER_CTA 8
#define SEGS 8
#define SEGSZ (NP / SEGS)   // 1024

__device__ float4 g_nbr[NCELLS][MAXN];
__device__ int    g_lidx[NCELLS][MAXN];
__device__ int    g_cnt[NCELLS];

// cell id = (cx*4 + cy)*4 + cz  -- must match query kernel
__global__ void __launch_bounds__(128)
build_kernel(const float* __restrict__ x)
{
    __shared__ int s_red[4];
    __shared__ int s_wcnt[4];

    const int cell = blockIdx.x >> 3;
    const int seg  = blockIdx.x & 7;
    const int cz = cell & 3;
    const int cy = (cell >> 2) & 3;
    const int cx = (cell >> 4) & 3;
    const float lox = cx * 0.25f - SLOPW, hix = cx * 0.25f + 0.25f + SLOPW;
    const float loy = cy * 0.25f - SLOPW, hiy = cy * 0.25f + 0.25f + SLOPW;
    const float loz = cz * 0.25f - SLOPW, hiz = cz * 0.25f + 0.25f + SLOPW;

    const int lane = threadIdx.x & 31;
    const int warp = threadIdx.x >> 5;
    const unsigned lt = (1u << lane) - 1u;
    const int seg0 = seg * SEGSZ;

    // ---- phase 0: count points in [0, seg0) inside box (global offset) ----
    int pre = 0;
    for (int base = 0; base < seg0; base += 128) {
        const int i = base + threadIdx.x;
        const float px = x[3 * i + 0];
        const float py = x[3 * i + 1];
        const float pz = x[3 * i + 2];
        const bool in = (px >= lox && px <= hix &&
                         py >= loy && py <= hiy &&
                         pz >= loz && pz <= hiz);
        pre += in ? 1 : 0;
    }
    // warp reduce + block reduce
    for (int o = 16; o > 0; o >>= 1) pre += __shfl_down_sync(0xffffffffu, pre, o);
    if (lane == 0) s_red[warp] = pre;
    __syncthreads();
    const int block_off = s_red[0] + s_red[1] + s_red[2] + s_red[3];

    // ---- phase 1: per-warp counts within this segment ----
    const int w0 = seg0 + warp * (SEGSZ / 4);       // 256 pts per warp
    const int w1 = w0 + (SEGSZ / 4);
    int c = 0;
    for (int base = w0; base < w1; base += 32) {
        const int i = base + lane;
        const float px = x[3 * i + 0];
        const float py = x[3 * i + 1];
        const float pz = x[3 * i + 2];
        const bool in = (px >= lox && px <= hix &&
                         py >= loy && py <= hiy &&
                         pz >= loz && pz <= hiz);
        c += __popc(__ballot_sync(0xffffffffu, in));
    }
    if (lane == 0) s_wcnt[warp] = c;
    __syncthreads();
    int off = block_off;
    for (int w = 0; w < warp; w++) off += s_wcnt[w];

    // ---- phase 2: ordered compact of this warp's range ----
    int cnt = 0;
    for (int base = w0; base < w1; base += 32) {
        const int i = base + lane;
        const float px = x[3 * i + 0];
        const float py = x[3 * i + 1];
        const float pz = x[3 * i + 2];
        const bool in = (px >= lox && px <= hix &&
                         py >= loy && py <= hiy &&
                         pz >= loz && pz <= hiz);
        const unsigned m = __ballot_sync(0xffffffffu, in);
        if (in) {
            const int pos = off + cnt + __popc(m & lt);
            if (pos < MAXN) {
                const float ps = px * px + py * py + pz * pz;
                g_nbr[cell][pos] = make_float4(px, py, pz, ps);
                g_lidx[cell][pos] = i;
            }
        }
        cnt += __popc(m);
    }

    // last segment's CTA publishes the total count
    if (seg == SEGS - 1 && threadIdx.x == 0) {
        int tot = block_off + s_wcnt[0] + s_wcnt[1] + s_wcnt[2] + s_wcnt[3];
        g_cnt[cell] = tot < MAXN ? tot : MAXN;
    }
}

__global__ void __launch_bounds__(256)
bq_kernel(const float* __restrict__ x,
          const float* __restrict__ pg,
          float* __restrict__ out)
{
    __shared__ int scratch[WARPS_PER_CTA][16];
    __shared__ int s_ccnt[NCELLS];

    if (threadIdx.x < NCELLS) s_ccnt[threadIdx.x] = g_cnt[threadIdx.x];
    __syncthreads();

    const int lane   = threadIdx.x & 31;
    const int warp   = threadIdx.x >> 5;
    const int gwarp  = (blockIdx.x * blockDim.x + threadIdx.x) >> 5;
    const int nwarps = (gridDim.x * blockDim.x) >> 5;
    const unsigned lt_mask = (1u << lane) - 1u;

    for (int q = gwarp; q < NQ; q += nwarps) {
        const float qx = pg[3 * q + 0];
        const float qy = pg[3 * q + 1];
        const float qz = pg[3 * q + 2];
        const float q2 = qx * qx + qy * qy + qz * qz;

        int cx = (int)(qx * 4.0f); cx = cx < 0 ? 0 : (cx > 3 ? 3 : cx);
        int cy = (int)(qy * 4.0f); cy = cy < 0 ? 0 : (cy > 3 ? 3 : cy);
        int cz = (int)(qz * 4.0f); cz = cz < 0 ? 0 : (cz > 3 ? 3 : cz);
        const int cell = (cx * 4 + cy) * 4 + cz;
        const int n = s_ccnt[cell];
        const float4* __restrict__ lst  = g_nbr[cell];
        const int*    __restrict__ lidx = g_lidx[cell];

        int cnt = 0;

        // scan the cell list, 64 entries / iteration, 2 ILP streams
        for (int base = 0; base < n; base += 64) {
            const int eA = base + lane;
            const int eB = base + 32 + lane;
            const float4 A = (eA < n) ? lst[eA] : make_float4(0.f, 0.f, 0.f, 1e30f);
            const float4 B = (eB < n) ? lst[eB] : make_float4(0.f, 0.f, 0.f, 1e30f);

            const float dotA = qx * A.x + qy * A.y + qz * A.z;
            const float d2A  = q2 + A.w - 2.0f * dotA;
            const float dotB = qx * B.x + qy * B.y + qz * B.z;
            const float d2B  = q2 + B.w - 2.0f * dotB;

            const bool vA = (d2A <= R2C);
            const bool vB = (d2B <= R2C);
            const unsigned mA = __ballot_sync(0xffffffffu, vA);
            const unsigned mB = __ballot_sync(0xffffffffu, vB);

            if (mA | mB) {
                if (vA) {
                    const int slot = cnt + __popc(mA & lt_mask);
                    if (slot < KNN) scratch[warp][slot] = eA;
                }
                const int cA = cnt + __popc(mA);
                if (vB) {
                    const int slot = cA + __popc(mB & lt_mask);
                    if (slot < KNN) scratch[warp][slot] = eB;
                }
                cnt = cA + __popc(mB);
                if (cnt >= KNN) break;   // warp-uniform
            }
        }

        __syncwarp();

        // epilogue: lanes 0..9 emit mapping + coords
        const int c = cnt < KNN ? cnt : KNN;
        if (lane < KNN) {
            const bool found = (lane < c);
            int idx = 0;
            float px = 0.0f, py = 0.0f, pz = 0.0f;
            if (found) {
                const int e = scratch[warp][lane];
                const float4 P = lst[e];
                px = P.x; py = P.y; pz = P.z;
                idx = lidx[e];
            }
            out[(size_t)q * KNN + lane] = found ? (float)idx : 0.0f;
            float* oc = out + MAP_ELEMS + ((size_t)q * KNN + lane) * 3;
            oc[0] = px; oc[1] = py; oc[2] = pz;
        }
        __syncwarp();   // scratch reuse safety
    }
}

extern "C" void kernel_launch(void* const* d_in, const int* in_sizes, int n_in,
                              void* d_out, int out_size)
{
    const float* x  = (const float*)d_in[0];   // (1, 8192, 3)
    const float* pg = (const float*)d_in[1];   // (1, 64, 32, 16, 3)
    if (n_in >= 2 && in_sizes[0] == NQ * 3 && in_sizes[1] == NP * 3) {
        const float* t = x; x = pg; pg = t;
    }
    float* out = (float*)d_out;

    build_kernel<<<NCELLS * SEGS, 128>>>(x);
    bq_kernel<<<888, 256>>>(x, pg, out);
}